// round 13
// baseline (speedup 1.0000x reference)
#include <cuda_runtime.h>
#include <cuda_fp16.h>
#include <cstdint>

#define HD    64
#define NV    16
#define TPB   128   // threads per CTA = samples per tile (M)
#define NCTA  592   // 148 SMs * 4 CTAs -> one resident wave
#define NTMAX 8     // max tiles owned per CTA per chunk (4096/592 = 6.9)

typedef unsigned long long u64;

// ---------------- helpers ----------------
__device__ __forceinline__ uint32_t smem_u32(const void* p) {
    uint32_t a;
    asm("{ .reg .u64 t; cvta.to.shared.u64 t, %1; cvt.u32.u64 %0, t; }" : "=r"(a) : "l"(p));
    return a;
}
__device__ __forceinline__ void ldmx4(uint32_t& r0, uint32_t& r1, uint32_t& r2, uint32_t& r3,
                                      uint32_t addr) {
    asm volatile("ldmatrix.sync.aligned.m8n8.x4.shared.b16 {%0,%1,%2,%3}, [%4];"
                 : "=r"(r0), "=r"(r1), "=r"(r2), "=r"(r3) : "r"(addr));
}
__device__ __forceinline__ void mma_f16(float* c, const uint32_t* a,
                                        uint32_t b0, uint32_t b1) {
    asm volatile("mma.sync.aligned.m16n8k16.row.col.f32.f16.f16.f32 "
                 "{%0,%1,%2,%3}, {%4,%5,%6,%7}, {%8,%9}, {%0,%1,%2,%3};"
                 : "+f"(c[0]), "+f"(c[1]), "+f"(c[2]), "+f"(c[3])
                 : "r"(a[0]), "r"(a[1]), "r"(a[2]), "r"(a[3]), "r"(b0), "r"(b1));
}
// packed f32x2 fma (sm_100)
__device__ __forceinline__ u64 fma2(u64 a, u64 b, u64 c) {
    u64 d;
    asm("fma.rn.f32x2 %0, %1, %2, %3;" : "=l"(d) : "l"(a), "l"(b), "l"(c));
    return d;
}
__device__ __forceinline__ u64 dup2(float x) {
    u64 d;
    asm("mov.b64 %0, {%1, %1};" : "=l"(d) : "f"(x));
    return d;
}
// unpack f32x2 pair, convert to f16x2 with fused relu: lo lane -> lo half
__device__ __forceinline__ uint32_t cvt_relu_pack(u64 h) {
    uint32_t r;
    asm("{ .reg .f32 lo, hi; mov.b64 {lo, hi}, %1; cvt.rn.relu.f16x2.f32 %0, hi, lo; }"
        : "=r"(r) : "l"(h));
    return r;
}
__device__ __forceinline__ void cp_async16(uint32_t smem_dst, const void* gmem_src) {
    asm volatile("cp.async.cg.shared.global [%0], [%1], 16;"
                 :: "r"(smem_dst), "l"(gmem_src) : "memory");
}

// ---------------- prepared weights ----------------
struct SmallV {
    float4 l1w[32];     // {ws[2c], ws[2c+1], we[2c], we[2c+1]}
    float2 l1b[32];     // {b1[2c], b1[2c+1]}
    float2 b2w3[HD];    // {B2[j], W3[j]}
    float b3;
    float std_;
    float pad[6];
};                       // 1312 B = 82 * 16
__device__ __align__(16) SmallV g_small[NV];
// W2^T (rows j = output, cols k = input) as swizzled fp16 smem image.
__device__ __align__(16) __half g_W2T[NV][HD * HD];

__global__ void prep_kernel(
    const float* __restrict__ stds,
    const float* __restrict__ w0_1, const float* __restrict__ b0_1,
    const float* __restrict__ w0_2, const float* __restrict__ b0_2,
    const float* __restrict__ w0_3, const float* __restrict__ b0_3,
    const float* __restrict__ W1,   const float* __restrict__ B1,
    const float* __restrict__ W2,   const float* __restrict__ B2,
    const float* __restrict__ W3,   const float* __restrict__ B3)
{
    const int v = blockIdx.x;
    const int tid = threadIdx.x;
    const float* w2 = (v == 0) ? w0_2 : W2 + (size_t)(v - 1) * HD * HD;  // [k][j]

    for (int t = tid; t < HD * HD; t += blockDim.x) {
        int k = t / HD, j = t % HD;
        float x = w2[k * HD + j];
        int idx = j * HD + (((k >> 3) ^ (j & 7)) << 3) + (k & 7);
        g_W2T[v][idx] = __float2half_rn(x);
    }
    SmallV* sv = &g_small[v];
    if (tid < 32) {
        int c = tid;
        float ws0, ws1, we0, we1, b10, b11;
        if (v == 0) {
            ws0 = ws1 = 0.0f;
            we0 = w0_1[2 * c]; we1 = w0_1[2 * c + 1];
            b10 = b0_1[2 * c]; b11 = b0_1[2 * c + 1];
        } else {
            int i = v - 1;
            ws0 = W1[(size_t)i * 2 * HD + 2 * c];
            ws1 = W1[(size_t)i * 2 * HD + 2 * c + 1];
            we0 = W1[(size_t)i * 2 * HD + HD + 2 * c];
            we1 = W1[(size_t)i * 2 * HD + HD + 2 * c + 1];
            b10 = B1[(size_t)i * HD + 2 * c];
            b11 = B1[(size_t)i * HD + 2 * c + 1];
        }
        sv->l1w[c] = make_float4(ws0, ws1, we0, we1);
        sv->l1b[c] = make_float2(b10, b11);
    }
    if (tid < HD) {
        if (v == 0) {
            sv->b2w3[tid] = make_float2(b0_2[tid], w0_3[tid]);
            if (tid == 0) { sv->b3 = b0_3[0]; sv->std_ = fabsf(stds[0]); }
        } else {
            int i = v - 1;
            sv->b2w3[tid] = make_float2(B2[(size_t)i * HD + tid], W3[(size_t)i * HD + tid]);
            if (tid == 0) { sv->b3 = B3[i]; sv->std_ = fabsf(stds[v]); }
        }
    }
}

// ---------------- fused persistent kernel ----------------
struct __align__(128) Stage {
    __half w[HD * HD];   // 8 KB, W2^T (swizzled fp16)
    SmallV sv;           // 1312 B
};

__global__ __launch_bounds__(TPB, 4)
void ncm_fused_kernel(const float* __restrict__ noise, float* __restrict__ out,
                      int nsamp, int ntiles)
{
    __shared__ Stage sStg[2];                 // ~18.6 KB
    __shared__ float sCar[NTMAX][TPB];        // 4 KB carry per owned tile

    const int tid  = threadIdx.x;
    const int w    = tid >> 5;
    const int lane = tid & 31;
    const int l7   = lane & 7;
    const int l3   = lane & 3;
    const int g    = lane >> 2;  // fragment row base 0..7
    const int mi   = lane >> 3;  // ldmatrix matrix index 0..3

    const int stride = gridDim.x;
    const int span   = stride * NTMAX;
    const int rowoff = w * 32 + g;            // row base within tile for this lane

    for (int cs = 0; cs < ntiles; cs += span) {
        // prologue: prefetch stage for v=0
        {
            const uint4* srcw = (const uint4*)&g_W2T[0][0];
            uint4* dstw = (uint4*)&sStg[0].w[0];
            #pragma unroll
            for (int c = 0; c < 4; c++)
                cp_async16(smem_u32(dstw + tid + c * TPB), srcw + tid + c * TPB);
            if (tid < 82)
                cp_async16(smem_u32(((uint4*)&sStg[0].sv) + tid), ((const uint4*)&g_small[0]) + tid);
            asm volatile("cp.async.commit_group;" ::: "memory");
        }

        for (int v = 0; v < NV; v++) {
            // prefetch v+1 into the other stage buffer
            if (v + 1 < NV) {
                Stage* nx = &sStg[(v + 1) & 1];
                const uint4* srcw = (const uint4*)&g_W2T[v + 1][0];
                uint4* dstw = (uint4*)&nx->w[0];
                #pragma unroll
                for (int c = 0; c < 4; c++)
                    cp_async16(smem_u32(dstw + tid + c * TPB), srcw + tid + c * TPB);
                if (tid < 82)
                    cp_async16(smem_u32(((uint4*)&nx->sv) + tid), ((const uint4*)&g_small[v + 1]) + tid);
                asm volatile("cp.async.commit_group;" ::: "memory");
                asm volatile("cp.async.wait_group 1;" ::: "memory");
            } else {
                asm volatile("cp.async.wait_group 0;" ::: "memory");
            }
            __syncthreads();   // stage v visible; prev-v readers done

            const Stage* st = &sStg[v & 1];
            const SmallV& sv = st->sv;
            const uint32_t sWh_b = smem_u32(&st->w[0]);
            const float stdv = sv.std_;
            const float b3   = sv.b3;
            const float* noise_v = noise + (size_t)v * nsamp;
            float* out_v = out + (size_t)v * nsamp;

            // ldmatrix base addresses for this lane (jt selects +jt*1024)
            const uint32_t badr0 = sWh_b + (uint32_t)(l7 * 128) + (uint32_t)(((0 + mi) ^ l7) * 16);
            const uint32_t badr1 = sWh_b + (uint32_t)(l7 * 128) + (uint32_t)(((4 + mi) ^ l7) * 16);

            // ---- B fragments for jtp 0,1 resident (tile-invariant) ----
            uint32_t bh[2][2][8];
            #pragma unroll
            for (int jtp = 0; jtp < 2; jtp++)
                #pragma unroll
                for (int jt2 = 0; jt2 < 2; jt2++) {
                    const uint32_t off = (uint32_t)((2 * jtp + jt2) * 1024);
                    ldmx4(bh[jtp][jt2][0], bh[jtp][jt2][1], bh[jtp][jt2][2], bh[jtp][jt2][3], badr0 + off);
                    ldmx4(bh[jtp][jt2][4], bh[jtp][jt2][5], bh[jtp][jt2][6], bh[jtp][jt2][7], badr1 + off);
                }

            // prefetch first tile's noise
            float er[4], ern[4];
            {
                int t0 = cs + blockIdx.x;
                if (t0 < ntiles) {
                    int rb = t0 * TPB + rowoff;
                    #pragma unroll
                    for (int q = 0; q < 4; q++) {
                        int r = rb + 8 * q;
                        er[q] = (r < nsamp) ? noise_v[r] * stdv : 0.0f;
                    }
                }
            }

            #pragma unroll 1
            for (int i = 0; i < NTMAX; i++) {
                const int t = cs + blockIdx.x + i * stride;
                if (t >= ntiles) break;

                // prefetch next tile's noise
                const int tn = t + stride;
                if (i + 1 < NTMAX && tn < ntiles) {
                    int rbn = tn * TPB + rowoff;
                    #pragma unroll
                    for (int q = 0; q < 4; q++) {
                        int r = rbn + 8 * q;
                        ern[q] = (r < nsamp) ? noise_v[r] * stdv : 0.0f;
                    }
                }

                // carry for the 4 fragment rows (warp-local smem, v=0 -> 0)
                u64 crd[4], erd[4];
                #pragma unroll
                for (int q = 0; q < 4; q++) {
                    float c = (v > 0) ? sCar[i][rowoff + 8 * q] : 0.0f;
                    crd[q] = dup2(c);
                    erd[q] = dup2(er[q]);
                }

                // ---- layer 1: packed f32x2 FMA + fused relu/pack to f16x2 ----
                uint32_t ah[2][4][4];
                #pragma unroll
                for (int kt = 0; kt < 4; kt++) {
                    ulonglong2 wAp = *(const ulonglong2*)&sv.l1w[8 * kt + l3];      // {ws01, we01}
                    u64       bAp = *(const u64*)&sv.l1b[8 * kt + l3];
                    ulonglong2 wBp = *(const ulonglong2*)&sv.l1w[8 * kt + l3 + 4];
                    u64       bBp = *(const u64*)&sv.l1b[8 * kt + l3 + 4];
                    #pragma unroll
                    for (int q = 0; q < 4; q++) {
                        const int mt = q >> 1, idx = q & 1;
                        u64 hA = fma2(crd[q], wAp.x, fma2(erd[q], wAp.y, bAp));
                        ah[mt][kt][idx] = cvt_relu_pack(hA);
                        u64 hB = fma2(crd[q], wBp.x, fma2(erd[q], wBp.y, bBp));
                        ah[mt][kt][2 + idx] = cvt_relu_pack(hB);
                    }
                }

                // ---- GEMM: D = B2 + A*B; jtp 0,1 from regs, jtp 2,3 re-loaded ----
                float p[2][2] = {{0, 0}, {0, 0}};
                #pragma unroll
                for (int jtp = 0; jtp < 4; jtp++) {
                    uint32_t bt[2][8];
                    const uint32_t (*bp)[8];
                    if (jtp < 2) {
                        bp = bh[jtp];
                    } else {
                        #pragma unroll
                        for (int jt2 = 0; jt2 < 2; jt2++) {
                            const uint32_t off = (uint32_t)((2 * jtp + jt2) * 1024);
                            ldmx4(bt[jt2][0], bt[jt2][1], bt[jt2][2], bt[jt2][3], badr0 + off);
                            ldmx4(bt[jt2][4], bt[jt2][5], bt[jt2][6], bt[jt2][7], badr1 + off);
                        }
                        bp = bt;
                    }

                    float2 bw0[2], bw1[2];
                    #pragma unroll
                    for (int jt2 = 0; jt2 < 2; jt2++) {
                        int j0 = (2 * jtp + jt2) * 8 + 2 * l3;
                        bw0[jt2] = sv.b2w3[j0];
                        bw1[jt2] = sv.b2w3[j0 + 1];
                    }

                    float acc[2][2][4];
                    #pragma unroll
                    for (int jt2 = 0; jt2 < 2; jt2++)
                        #pragma unroll
                        for (int mt = 0; mt < 2; mt++) {
                            acc[jt2][mt][0] = bw0[jt2].x;
                            acc[jt2][mt][1] = bw1[jt2].x;
                            acc[jt2][mt][2] = bw0[jt2].x;
                            acc[jt2][mt][3] = bw1[jt2].x;
                        }

                    #pragma unroll
                    for (int kt = 0; kt < 4; kt++)
                        #pragma unroll
                        for (int jt2 = 0; jt2 < 2; jt2++)
                            #pragma unroll
                            for (int mt = 0; mt < 2; mt++)
                                mma_f16(acc[jt2][mt], ah[mt][kt],
                                        bp[jt2][2 * kt], bp[jt2][2 * kt + 1]);

                    #pragma unroll
                    for (int jt2 = 0; jt2 < 2; jt2++)
                        #pragma unroll
                        for (int mt = 0; mt < 2; mt++) {
                            p[mt][0] = fmaf(fmaxf(acc[jt2][mt][0], 0.0f), bw0[jt2].y, p[mt][0]);
                            p[mt][0] = fmaf(fmaxf(acc[jt2][mt][1], 0.0f), bw1[jt2].y, p[mt][0]);
                            p[mt][1] = fmaf(fmaxf(acc[jt2][mt][2], 0.0f), bw0[jt2].y, p[mt][1]);
                            p[mt][1] = fmaf(fmaxf(acc[jt2][mt][3], 0.0f), bw1[jt2].y, p[mt][1]);
                        }
                }

                // ---- reduce across quad; l3==0 lanes hold rows g, g+8, g+16, g+24 ----
                #pragma unroll
                for (int mt = 0; mt < 2; mt++)
                    #pragma unroll
                    for (int q = 0; q < 2; q++) {
                        p[mt][q] += __shfl_xor_sync(0xffffffffu, p[mt][q], 1);
                        p[mt][q] += __shfl_xor_sync(0xffffffffu, p[mt][q], 2);
                    }
                if (l3 == 0) {
                    float v0 = p[0][0] + b3, v1 = p[0][1] + b3;
                    float v2 = p[1][0] + b3, v3 = p[1][1] + b3;
                    int base = w * 32 + g;
                    sCar[i][base]      = v0;
                    sCar[i][base + 8]  = v1;
                    sCar[i][base + 16] = v2;
                    sCar[i][base + 24] = v3;
                    int rbw = t * TPB + base;
                    if (rbw      < nsamp) out_v[rbw]      = v0;
                    if (rbw + 8  < nsamp) out_v[rbw + 8]  = v1;
                    if (rbw + 16 < nsamp) out_v[rbw + 16] = v2;
                    if (rbw + 24 < nsamp) out_v[rbw + 24] = v3;
                }
                __syncwarp();

                #pragma unroll
                for (int q = 0; q < 4; q++) er[q] = ern[q];
            }

            __syncthreads();   // all warps done with stage v before overwrite
        }
    }
}

extern "C" void kernel_launch(void* const* d_in, const int* in_sizes, int n_in,
                              void* d_out, int out_size) {
    const float* noise = (const float*)d_in[0];
    const float* stds  = (const float*)d_in[1];
    const float* w0_1  = (const float*)d_in[2];
    const float* b0_1  = (const float*)d_in[3];
    const float* w0_2  = (const float*)d_in[4];
    const float* b0_2  = (const float*)d_in[5];
    const float* w0_3  = (const float*)d_in[6];
    const float* b0_3  = (const float*)d_in[7];
    const float* W1    = (const float*)d_in[8];
    const float* B1    = (const float*)d_in[9];
    const float* W2    = (const float*)d_in[10];
    const float* B2    = (const float*)d_in[11];
    const float* W3    = (const float*)d_in[12];
    const float* B3    = (const float*)d_in[13];
    float* out = (float*)d_out;

    const int nsamp  = in_sizes[0] / NV;
    const int ntiles = (nsamp + TPB - 1) / TPB;
    const int grid   = (ntiles < NCTA) ? ntiles : NCTA;

    prep_kernel<<<NV, 256>>>(stds, w0_1, b0_1, w0_2, b0_2, w0_3, b0_3,
                             W1, B1, W2, B2, W3, B3);
    ncm_fused_kernel<<<grid, TPB>>>(noise, out, nsamp, ntiles);
}

// round 16
// speedup vs baseline: 1.0120x; 1.0120x over previous
#include <cuda_runtime.h>
#include <cuda_fp16.h>
#include <cstdint>

#define HD    64
#define NV    16
#define TPB   128   // threads per CTA = samples per tile (M)
#define NCTA  444   // 148 SMs * 3 CTAs -> one resident wave
#define NTMAX 10    // max tiles owned per CTA per chunk

typedef unsigned long long u64;

// ---------------- helpers ----------------
__device__ __forceinline__ uint32_t smem_u32(const void* p) {
    uint32_t a;
    asm("{ .reg .u64 t; cvta.to.shared.u64 t, %1; cvt.u32.u64 %0, t; }" : "=r"(a) : "l"(p));
    return a;
}
__device__ __forceinline__ void ldmx4(uint32_t& r0, uint32_t& r1, uint32_t& r2, uint32_t& r3,
                                      uint32_t addr) {
    asm volatile("ldmatrix.sync.aligned.m8n8.x4.shared.b16 {%0,%1,%2,%3}, [%4];"
                 : "=r"(r0), "=r"(r1), "=r"(r2), "=r"(r3) : "r"(addr));
}
__device__ __forceinline__ void mma_f16(float* c, const uint32_t* a,
                                        uint32_t b0, uint32_t b1) {
    asm volatile("mma.sync.aligned.m16n8k16.row.col.f32.f16.f16.f32 "
                 "{%0,%1,%2,%3}, {%4,%5,%6,%7}, {%8,%9}, {%0,%1,%2,%3};"
                 : "+f"(c[0]), "+f"(c[1]), "+f"(c[2]), "+f"(c[3])
                 : "r"(a[0]), "r"(a[1]), "r"(a[2]), "r"(a[3]), "r"(b0), "r"(b1));
}
// packed f32x2 fma (sm_100)
__device__ __forceinline__ u64 fma2(u64 a, u64 b, u64 c) {
    u64 d;
    asm("fma.rn.f32x2 %0, %1, %2, %3;" : "=l"(d) : "l"(a), "l"(b), "l"(c));
    return d;
}
__device__ __forceinline__ u64 dup2(float x) {
    u64 d;
    asm("mov.b64 %0, {%1, %1};" : "=l"(d) : "f"(x));
    return d;
}
// unpack f32x2 pair, convert to f16x2 with fused relu: lo lane -> lo half
__device__ __forceinline__ uint32_t cvt_relu_pack(u64 h) {
    uint32_t r;
    asm("{ .reg .f32 lo, hi; mov.b64 {lo, hi}, %1; cvt.rn.relu.f16x2.f32 %0, hi, lo; }"
        : "=r"(r) : "l"(h));
    return r;
}
__device__ __forceinline__ void cp_async16(uint32_t smem_dst, const void* gmem_src) {
    asm volatile("cp.async.cg.shared.global [%0], [%1], 16;"
                 :: "r"(smem_dst), "l"(gmem_src) : "memory");
}

// ---------------- prepared weights ----------------
struct SmallV {
    float4 l1w[32];     // {ws[2c], ws[2c+1], we[2c], we[2c+1]}
    float2 l1b[32];     // {b1[2c], b1[2c+1]}
    float2 b2w3[HD];    // {B2[j], W3[j]}
    float b3;
    float std_;
    float pad[6];
};                       // 1312 B = 82 * 16
__device__ __align__(16) SmallV g_small[NV];
// W2^T (rows j = output, cols k = input) as swizzled fp16 smem image.
__device__ __align__(16) __half g_W2T[NV][HD * HD];

__global__ void prep_kernel(
    const float* __restrict__ stds,
    const float* __restrict__ w0_1, const float* __restrict__ b0_1,
    const float* __restrict__ w0_2, const float* __restrict__ b0_2,
    const float* __restrict__ w0_3, const float* __restrict__ b0_3,
    const float* __restrict__ W1,   const float* __restrict__ B1,
    const float* __restrict__ W2,   const float* __restrict__ B2,
    const float* __restrict__ W3,   const float* __restrict__ B3)
{
    const int v = blockIdx.x;
    const int tid = threadIdx.x;
    const float* w2 = (v == 0) ? w0_2 : W2 + (size_t)(v - 1) * HD * HD;  // [k][j]

    for (int t = tid; t < HD * HD; t += blockDim.x) {
        int k = t / HD, j = t % HD;
        float x = w2[k * HD + j];
        int idx = j * HD + (((k >> 3) ^ (j & 7)) << 3) + (k & 7);
        g_W2T[v][idx] = __float2half_rn(x);
    }
    SmallV* sv = &g_small[v];
    if (tid < 32) {
        int c = tid;
        float ws0, ws1, we0, we1, b10, b11;
        if (v == 0) {
            ws0 = ws1 = 0.0f;
            we0 = w0_1[2 * c]; we1 = w0_1[2 * c + 1];
            b10 = b0_1[2 * c]; b11 = b0_1[2 * c + 1];
        } else {
            int i = v - 1;
            ws0 = W1[(size_t)i * 2 * HD + 2 * c];
            ws1 = W1[(size_t)i * 2 * HD + 2 * c + 1];
            we0 = W1[(size_t)i * 2 * HD + HD + 2 * c];
            we1 = W1[(size_t)i * 2 * HD + HD + 2 * c + 1];
            b10 = B1[(size_t)i * HD + 2 * c];
            b11 = B1[(size_t)i * HD + 2 * c + 1];
        }
        sv->l1w[c] = make_float4(ws0, ws1, we0, we1);
        sv->l1b[c] = make_float2(b10, b11);
    }
    if (tid < HD) {
        if (v == 0) {
            sv->b2w3[tid] = make_float2(b0_2[tid], w0_3[tid]);
            if (tid == 0) { sv->b3 = b0_3[0]; sv->std_ = fabsf(stds[0]); }
        } else {
            int i = v - 1;
            sv->b2w3[tid] = make_float2(B2[(size_t)i * HD + tid], W3[(size_t)i * HD + tid]);
            if (tid == 0) { sv->b3 = B3[i]; sv->std_ = fabsf(stds[v]); }
        }
    }
}

// ---------------- fused persistent kernel ----------------
struct __align__(128) Stage {
    __half w[HD * HD];   // 8 KB, W2^T (swizzled fp16)
    SmallV sv;           // 1312 B
};

__global__ __launch_bounds__(TPB, 3)
void ncm_fused_kernel(const float* __restrict__ noise, float* __restrict__ out,
                      int nsamp, int ntiles)
{
    __shared__ Stage sStg[2];                 // ~18.6 KB
    __shared__ float sCar[NTMAX][TPB];        // 5 KB carry per owned tile

    const int tid  = threadIdx.x;
    const int w    = tid >> 5;
    const int lane = tid & 31;
    const int l7   = lane & 7;
    const int l3   = lane & 3;
    const int g    = lane >> 2;  // fragment row base 0..7
    const int mi   = lane >> 3;  // ldmatrix matrix index 0..3

    const int stride = gridDim.x;
    const int span   = stride * NTMAX;
    const int rowoff = w * 32 + g;            // row base within tile for this lane

    for (int cs = 0; cs < ntiles; cs += span) {
        // prologue: prefetch stage for v=0
        {
            const uint4* srcw = (const uint4*)&g_W2T[0][0];
            uint4* dstw = (uint4*)&sStg[0].w[0];
            #pragma unroll
            for (int c = 0; c < 4; c++)
                cp_async16(smem_u32(dstw + tid + c * TPB), srcw + tid + c * TPB);
            if (tid < 82)
                cp_async16(smem_u32(((uint4*)&sStg[0].sv) + tid), ((const uint4*)&g_small[0]) + tid);
            asm volatile("cp.async.commit_group;" ::: "memory");
        }

        for (int v = 0; v < NV; v++) {
            // prefetch v+1 into the other stage buffer
            if (v + 1 < NV) {
                Stage* nx = &sStg[(v + 1) & 1];
                const uint4* srcw = (const uint4*)&g_W2T[v + 1][0];
                uint4* dstw = (uint4*)&nx->w[0];
                #pragma unroll
                for (int c = 0; c < 4; c++)
                    cp_async16(smem_u32(dstw + tid + c * TPB), srcw + tid + c * TPB);
                if (tid < 82)
                    cp_async16(smem_u32(((uint4*)&nx->sv) + tid), ((const uint4*)&g_small[v + 1]) + tid);
                asm volatile("cp.async.commit_group;" ::: "memory");
                asm volatile("cp.async.wait_group 1;" ::: "memory");
            } else {
                asm volatile("cp.async.wait_group 0;" ::: "memory");
            }
            __syncthreads();   // stage v visible; prev-v readers done

            const Stage* st = &sStg[v & 1];
            const SmallV& sv = st->sv;
            const uint32_t sWh_b = smem_u32(&st->w[0]);
            const float stdv = sv.std_;
            const float b3   = sv.b3;
            const float* noise_v = noise + (size_t)v * nsamp;
            float* out_v = out + (size_t)v * nsamp;

            // ---- load ALL B fragments for this variable (tile-invariant) ----
            uint32_t bh[4][2][8];
            {
                const uint32_t badr0 = sWh_b + (uint32_t)(l7 * 128) + (uint32_t)(((0 + mi) ^ l7) * 16);
                const uint32_t badr1 = sWh_b + (uint32_t)(l7 * 128) + (uint32_t)(((4 + mi) ^ l7) * 16);
                #pragma unroll
                for (int jtp = 0; jtp < 4; jtp++)
                    #pragma unroll
                    for (int jt2 = 0; jt2 < 2; jt2++) {
                        const uint32_t off = (uint32_t)((2 * jtp + jt2) * 1024);
                        ldmx4(bh[jtp][jt2][0], bh[jtp][jt2][1], bh[jtp][jt2][2], bh[jtp][jt2][3], badr0 + off);
                        ldmx4(bh[jtp][jt2][4], bh[jtp][jt2][5], bh[jtp][jt2][6], bh[jtp][jt2][7], badr1 + off);
                    }
            }

            // prefetch first tile's noise
            float er[4], ern[4];
            {
                int t0 = cs + blockIdx.x;
                if (t0 < ntiles) {
                    int rb = t0 * TPB + rowoff;
                    #pragma unroll
                    for (int q = 0; q < 4; q++) {
                        int r = rb + 8 * q;
                        er[q] = (r < nsamp) ? noise_v[r] * stdv : 0.0f;
                    }
                }
            }

            #pragma unroll 1
            for (int i = 0; i < NTMAX; i++) {
                const int t = cs + blockIdx.x + i * stride;
                if (t >= ntiles) break;

                // prefetch next tile's noise
                const int tn = t + stride;
                if (i + 1 < NTMAX && tn < ntiles) {
                    int rbn = tn * TPB + rowoff;
                    #pragma unroll
                    for (int q = 0; q < 4; q++) {
                        int r = rbn + 8 * q;
                        ern[q] = (r < nsamp) ? noise_v[r] * stdv : 0.0f;
                    }
                }

                // carry for the 4 fragment rows (warp-local smem, v=0 -> 0)
                u64 crd[4], erd[4];
                #pragma unroll
                for (int q = 0; q < 4; q++) {
                    float c = (v > 0) ? sCar[i][rowoff + 8 * q] : 0.0f;
                    crd[q] = dup2(c);
                    erd[q] = dup2(er[q]);
                }

                // ---- layer 1: packed f32x2 FMA + fused relu/pack to f16x2 ----
                uint32_t ah[2][4][4];
                #pragma unroll
                for (int kt = 0; kt < 4; kt++) {
                    ulonglong2 wAp = *(const ulonglong2*)&sv.l1w[8 * kt + l3];      // {ws01, we01}
                    u64       bAp = *(const u64*)&sv.l1b[8 * kt + l3];
                    ulonglong2 wBp = *(const ulonglong2*)&sv.l1w[8 * kt + l3 + 4];
                    u64       bBp = *(const u64*)&sv.l1b[8 * kt + l3 + 4];
                    #pragma unroll
                    for (int q = 0; q < 4; q++) {
                        const int mt = q >> 1, idx = q & 1;
                        u64 hA = fma2(crd[q], wAp.x, fma2(erd[q], wAp.y, bAp));
                        ah[mt][kt][idx] = cvt_relu_pack(hA);
                        u64 hB = fma2(crd[q], wBp.x, fma2(erd[q], wBp.y, bBp));
                        ah[mt][kt][2 + idx] = cvt_relu_pack(hB);
                    }
                }

                // ---- GEMM: two jt-pairs concurrently -> 8 independent acc chains ----
                float p[2][2] = {{0, 0}, {0, 0}};
                #pragma unroll
                for (int jpp = 0; jpp < 2; jpp++) {
                    float2 bw0[2][2], bw1[2][2];  // [jp2][jt2]
                    #pragma unroll
                    for (int jp2 = 0; jp2 < 2; jp2++)
                        #pragma unroll
                        for (int jt2 = 0; jt2 < 2; jt2++) {
                            int j0 = ((2 * jpp + jp2) * 2 + jt2) * 8 + 2 * l3;
                            bw0[jp2][jt2] = sv.b2w3[j0];
                            bw1[jp2][jt2] = sv.b2w3[j0 + 1];
                        }

                    float acc[2][2][2][4];  // [jp2][jt2][mt][quad], bias folded in
                    #pragma unroll
                    for (int jp2 = 0; jp2 < 2; jp2++)
                        #pragma unroll
                        for (int jt2 = 0; jt2 < 2; jt2++)
                            #pragma unroll
                            for (int mt = 0; mt < 2; mt++) {
                                acc[jp2][jt2][mt][0] = bw0[jp2][jt2].x;
                                acc[jp2][jt2][mt][1] = bw1[jp2][jt2].x;
                                acc[jp2][jt2][mt][2] = bw0[jp2][jt2].x;
                                acc[jp2][jt2][mt][3] = bw1[jp2][jt2].x;
                            }

                    // kt outer: 8 MMAs per step round-robin over (jp2, jt2, mt)
                    #pragma unroll
                    for (int kt = 0; kt < 4; kt++)
                        #pragma unroll
                        for (int jp2 = 0; jp2 < 2; jp2++)
                            #pragma unroll
                            for (int jt2 = 0; jt2 < 2; jt2++)
                                #pragma unroll
                                for (int mt = 0; mt < 2; mt++)
                                    mma_f16(acc[jp2][jt2][mt], ah[mt][kt],
                                            bh[2 * jpp + jp2][jt2][2 * kt],
                                            bh[2 * jpp + jp2][jt2][2 * kt + 1]);

                    // epilogue for both pairs
                    #pragma unroll
                    for (int jp2 = 0; jp2 < 2; jp2++)
                        #pragma unroll
                        for (int jt2 = 0; jt2 < 2; jt2++)
                            #pragma unroll
                            for (int mt = 0; mt < 2; mt++) {
                                p[mt][0] = fmaf(fmaxf(acc[jp2][jt2][mt][0], 0.0f), bw0[jp2][jt2].y, p[mt][0]);
                                p[mt][0] = fmaf(fmaxf(acc[jp2][jt2][mt][1], 0.0f), bw1[jp2][jt2].y, p[mt][0]);
                                p[mt][1] = fmaf(fmaxf(acc[jp2][jt2][mt][2], 0.0f), bw0[jp2][jt2].y, p[mt][1]);
                                p[mt][1] = fmaf(fmaxf(acc[jp2][jt2][mt][3], 0.0f), bw1[jp2][jt2].y, p[mt][1]);
                            }
                }

                // ---- reduce across quad; l3==0 lanes hold rows g, g+8, g+16, g+24 ----
                #pragma unroll
                for (int mt = 0; mt < 2; mt++)
                    #pragma unroll
                    for (int q = 0; q < 2; q++) {
                        p[mt][q] += __shfl_xor_sync(0xffffffffu, p[mt][q], 1);
                        p[mt][q] += __shfl_xor_sync(0xffffffffu, p[mt][q], 2);
                    }
                if (l3 == 0) {
                    float v0 = p[0][0] + b3, v1 = p[0][1] + b3;
                    float v2 = p[1][0] + b3, v3 = p[1][1] + b3;
                    int base = w * 32 + g;
                    sCar[i][base]      = v0;
                    sCar[i][base + 8]  = v1;
                    sCar[i][base + 16] = v2;
                    sCar[i][base + 24] = v3;
                    int rbw = t * TPB + base;
                    if (rbw      < nsamp) out_v[rbw]      = v0;
                    if (rbw + 8  < nsamp) out_v[rbw + 8]  = v1;
                    if (rbw + 16 < nsamp) out_v[rbw + 16] = v2;
                    if (rbw + 24 < nsamp) out_v[rbw + 24] = v3;
                }
                __syncwarp();

                #pragma unroll
                for (int q = 0; q < 4; q++) er[q] = ern[q];
            }

            __syncthreads();   // all warps done with stage v before overwrite
        }
    }
}

extern "C" void kernel_launch(void* const* d_in, const int* in_sizes, int n_in,
                              void* d_out, int out_size) {
    const float* noise = (const float*)d_in[0];
    const float* stds  = (const float*)d_in[1];
    const float* w0_1  = (const float*)d_in[2];
    const float* b0_1  = (const float*)d_in[3];
    const float* w0_2  = (const float*)d_in[4];
    const float* b0_2  = (const float*)d_in[5];
    const float* w0_3  = (const float*)d_in[6];
    const float* b0_3  = (const float*)d_in[7];
    const float* W1    = (const float*)d_in[8];
    const float* B1    = (const float*)d_in[9];
    const float* W2    = (const float*)d_in[10];
    const float* B2    = (const float*)d_in[11];
    const float* W3    = (const float*)d_in[12];
    const float* B3    = (const float*)d_in[13];
    float* out = (float*)d_out;

    const int nsamp  = in_sizes[0] / NV;
    const int ntiles = (nsamp + TPB - 1) / TPB;
    const int grid   = (ntiles < NCTA) ? ntiles : NCTA;

    prep_kernel<<<NV, 256>>>(stds, w0_1, b0_1, w0_2, b0_2, w0_3, b0_3,
                             W1, B1, W2, B2, W3, B3);
    ncm_fused_kernel<<<grid, TPB>>>(noise, out, nsamp, ntiles);
}